// round 14
// baseline (speedup 1.0000x reference)
#include <cuda_runtime.h>
#include <cuda_fp16.h>
#include <cstdint>

// features: [32, 768, 32, 32] -> F[b, c, hw], hw = 1024
// query:    [32, 16, 32, 32]  -> Q[b, q, hw]
// W:        [64, 16, 768]     -> A[r, c], r = k*16+q  (1024 x 768)
//
// dist2[b,k] = sum_{q,hw} (A@F_b - Q)^2 ; codes = argmin_k ; sel = recompute.
// GEMM in pure fp16 mma.sync (dist2 err std ~0.14 << argmin gap ~150).
// sel + commit_loss recomputed EXACTLY in fp32, so output precision is fp32.

#define FN   (32 * 768 * 1024)
#define WN   (1024 * 768)

__device__ __half g_Fh[FN];
__device__ __half g_Wh[WN];
__device__ float g_dist2_part[32 * 512];   // [b][k(64)][hwtile(8)]
__device__ int   g_codes[32];
__device__ float g_loss_part[512];

// ---------------- PTX helpers ----------------
__device__ __forceinline__ uint32_t smem_u32(const void* p) {
    uint32_t a;
    asm("{ .reg .u64 t; cvta.to.shared.u64 t, %1; cvt.u32.u64 %0, t; }" : "=r"(a) : "l"(p));
    return a;
}
__device__ __forceinline__ void cp16(uint32_t dst, const void* src) {
    asm volatile("cp.async.cg.shared.global [%0], [%1], 16;" :: "r"(dst), "l"(src));
}
#define CP_COMMIT() asm volatile("cp.async.commit_group;" ::: "memory")
#define CP_WAIT(n)  asm volatile("cp.async.wait_group %0;" :: "n"(n) : "memory")

__device__ __forceinline__ void ldsm_x4(uint32_t addr, uint32_t* r) {
    asm volatile("ldmatrix.sync.aligned.m8n8.x4.shared.b16 {%0,%1,%2,%3}, [%4];"
                 : "=r"(r[0]), "=r"(r[1]), "=r"(r[2]), "=r"(r[3]) : "r"(addr));
}
__device__ __forceinline__ void ldsm_x4_t(uint32_t addr, uint32_t* r) {
    asm volatile("ldmatrix.sync.aligned.m8n8.x4.trans.shared.b16 {%0,%1,%2,%3}, [%4];"
                 : "=r"(r[0]), "=r"(r[1]), "=r"(r[2]), "=r"(r[3]) : "r"(addr));
}
__device__ __forceinline__ void mma_f16(float* c, const uint32_t* a, const uint32_t* b) {
    asm volatile(
        "mma.sync.aligned.m16n8k16.row.col.f32.f16.f16.f32 "
        "{%0,%1,%2,%3},{%4,%5,%6,%7},{%8,%9},{%0,%1,%2,%3};"
        : "+f"(c[0]), "+f"(c[1]), "+f"(c[2]), "+f"(c[3])
        : "r"(a[0]), "r"(a[1]), "r"(a[2]), "r"(a[3]), "r"(b[0]), "r"(b[1]));
}

// ---------------- fp32 -> fp16 pre-conversion (F and W in one launch) ----------------
#define CONV_F_BLOCKS 2048
#define CONV_W_BLOCKS 192
__global__ void conv_kernel(const float* __restrict__ F, const float* __restrict__ W) {
    if (blockIdx.x < CONV_F_BLOCKS) {
        const float4* src = (const float4*)F;
        __half2* h2 = reinterpret_cast<__half2*>(g_Fh);
        const int n4 = FN / 4;
        for (int i = blockIdx.x * blockDim.x + threadIdx.x; i < n4;
             i += CONV_F_BLOCKS * blockDim.x) {
            float4 v = src[i];
            h2[i * 2 + 0] = __floats2half2_rn(v.x, v.y);
            h2[i * 2 + 1] = __floats2half2_rn(v.z, v.w);
        }
    } else {
        const float4* src = (const float4*)W;
        __half2* h2 = reinterpret_cast<__half2*>(g_Wh);
        const int n4 = WN / 4;
        for (int i = (blockIdx.x - CONV_F_BLOCKS) * blockDim.x + threadIdx.x; i < n4;
             i += CONV_W_BLOCKS * blockDim.x) {
            float4 v = src[i];
            h2[i * 2 + 0] = __floats2half2_rn(v.x, v.y);
            h2[i * 2 + 1] = __floats2half2_rn(v.z, v.w);
        }
    }
}

// ---------------- dist GEMM: fp16 mma.sync (R8 structure, proven) ----------------
#define ST_B    10240
#define STAGE   18944
#define NSTAGE  5
#define DSMEM   (NSTAGE * STAGE + 64)

__device__ __forceinline__ void load_stage(
    int t, int kb, uint32_t sbase, int rowBase, int colBase, size_t Foff)
{
    #pragma unroll
    for (int it = 0; it < 4; ++it) {
        int o = it * 128 + t;
        int row = o >> 2, seg = o & 3;
        const __half* s = g_Wh + (size_t)(rowBase + row) * 768 + kb + seg * 8;
        cp16(sbase + row * 80 + seg * 16, s);
    }
    #pragma unroll
    for (int it = 0; it < 4; ++it) {
        int o = it * 128 + t;
        int row = o >> 4, seg = o & 15;
        const __half* s = g_Fh + Foff + (size_t)(kb + row) * 1024 + colBase + seg * 8;
        cp16(sbase + ST_B + row * 272 + seg * 16, s);
    }
}

__global__ __launch_bounds__(128, 2)
void dist_gemm_mma(const float* __restrict__ Q)
{
    extern __shared__ char smem[];
    const uint32_t sb = smem_u32(smem);
    float* sred = (float*)(smem + NSTAGE * STAGE);   // [8 k][2 colgrp]

    const int t    = threadIdx.x;
    const int wid  = t >> 5;
    const int lane = t & 31;
    const int wr   = wid & 1;
    const int wc   = wid >> 1;
    const int b       = blockIdx.z;
    const int rowBase = blockIdx.y * 128;
    const int colBase = blockIdx.x * 128;
    const size_t Foff = (size_t)b * 768 * 1024;

    uint32_t a_addr[4];
    #pragma unroll
    for (int rt = 0; rt < 4; ++rt) {
        int row = wr * 64 + rt * 16 + (lane & 15);
        a_addr[rt] = sb + row * 80 + ((lane >> 4) * 16);
    }
    uint32_t b_addr[4];
    #pragma unroll
    for (int p = 0; p < 4; ++p) {
        int n = wc * 64 + p * 16 + (lane >> 4) * 8;
        b_addr[p] = sb + ST_B + (lane & 15) * 272 + n * 2;
    }

    float acc[4][8][4];
    #pragma unroll
    for (int i = 0; i < 4; ++i)
        #pragma unroll
        for (int j = 0; j < 8; ++j)
            #pragma unroll
            for (int v = 0; v < 4; ++v) acc[i][j][v] = 0.0f;

    load_stage(t, 0, sb, rowBase, colBase, Foff);
    CP_COMMIT();
    load_stage(t, 32, sb + STAGE, rowBase, colBase, Foff);
    CP_COMMIT();
    load_stage(t, 64, sb + 2 * STAGE, rowBase, colBase, Foff);
    CP_COMMIT();

    for (int kt = 0; kt < 24; ++kt) {
        if (kt + 3 < 24)
            load_stage(t, (kt + 3) * 32, sb + ((kt + 3) % NSTAGE) * STAGE,
                       rowBase, colBase, Foff);
        CP_COMMIT();
        CP_WAIT(3);           // this warp's chunk-kt copies resident
        __syncthreads();      // -> ALL warps' chunk-kt copies visible

        const uint32_t soff = (kt % NSTAGE) * STAGE;
        #pragma unroll
        for (int ks = 0; ks < 2; ++ks) {
            uint32_t ah[4][4], bh[16];
            const uint32_t aoff = soff + ks * 32;
            const uint32_t boff = soff + ks * (16 * 272);
            #pragma unroll
            for (int rt = 0; rt < 4; ++rt)
                ldsm_x4(a_addr[rt] + aoff, ah[rt]);
            #pragma unroll
            for (int p = 0; p < 4; ++p)
                ldsm_x4_t(b_addr[p] + boff, &bh[p * 4]);
            #pragma unroll
            for (int rt = 0; rt < 4; ++rt)
                #pragma unroll
                for (int nt = 0; nt < 8; ++nt)
                    mma_f16(acc[rt][nt], ah[rt], &bh[nt * 2]);
        }
    }

    // ---- epilogue: (C - Q)^2, deterministic reduction per k-group ----
    const int qr0 = lane >> 2;
    const int cb  = colBase + wc * 64;
    float2 qa[8], qb[8];
    #pragma unroll
    for (int nt = 0; nt < 8; ++nt) {
        const float* q0 = Q + (size_t)b * 16384 + (size_t)qr0 * 1024 + cb + nt * 8 + (lane & 3) * 2;
        qa[nt] = *(const float2*)q0;
        qb[nt] = *(const float2*)(q0 + 8 * 1024);
    }
    __syncthreads();
    #pragma unroll
    for (int rt = 0; rt < 4; ++rt) {
        float rs = 0.0f;
        #pragma unroll
        for (int nt = 0; nt < 8; ++nt) {
            float d0 = acc[rt][nt][0] - qa[nt].x;
            float d1 = acc[rt][nt][1] - qa[nt].y;
            float d2 = acc[rt][nt][2] - qb[nt].x;
            float d3 = acc[rt][nt][3] - qb[nt].y;
            rs += d0 * d0 + d1 * d1 + d2 * d2 + d3 * d3;
        }
        #pragma unroll
        for (int off = 16; off > 0; off >>= 1)
            rs += __shfl_xor_sync(0xffffffffu, rs, off);
        if (lane == 0) sred[(wr * 4 + rt) * 2 + wc] = rs;
    }
    __syncthreads();
    if (t < 8) {
        float s = sred[t * 2 + 0] + sred[t * 2 + 1];
        const int k = blockIdx.y * 8 + t;
        g_dist2_part[b * 512 + k * 8 + blockIdx.x] = s;
    }
}

// ---------------- argmin: 1 block, warp-per-batch ----------------
__global__ __launch_bounds__(1024)
void argmin_kernel(float* __restrict__ out)
{
    const int b    = threadIdx.x >> 5;
    const int lane = threadIdx.x & 31;

    float v[2];
    #pragma unroll
    for (int j = 0; j < 2; ++j) {
        const int k = lane * 2 + j;
        const float4* p = (const float4*)(g_dist2_part + b * 512 + k * 8);
        float4 x = p[0], y = p[1];
        v[j] = (x.x + x.y) + (x.z + x.w) + (y.x + y.y) + (y.z + y.w);
    }
    float best = v[0] < v[1] ? v[0] : v[1];
    int   bi   = v[0] < v[1] ? lane * 2 : lane * 2 + 1;
    #pragma unroll
    for (int off = 16; off > 0; off >>= 1) {
        float ov = __shfl_xor_sync(0xffffffffu, best, off);
        int   oi = __shfl_xor_sync(0xffffffffu, bi,   off);
        if (ov < best || (ov == best && oi < bi)) { best = ov; bi = oi; }
    }
    if (lane == 0) {
        g_codes[b] = bi;
        out[524288 + b] = (float)bi;
    }
}

// ---------------- sel recompute (fp32 exact) + loss partials ----------------
// grid = (16 col-tiles x 32 batches), 256 threads = 32 lanes x 8 c-partitions.
// Each thread handles TWO columns (col, col+32): W loads (warp-uniform,
// L1-resident) amortize over 2 F streams -> ~40% fewer L1 wavefronts.
// 8-deep F batches per column (16 outstanding LDGs total, same MLP as R13).
__global__ __launch_bounds__(256, 3)
void sel_kernel(const float* __restrict__ F,
                const float* __restrict__ Q,
                const float* __restrict__ W,
                float* __restrict__ out)
{
    __shared__ float red[8][16][64];   // 32 KB
    const int b    = blockIdx.y;
    const int lane = threadIdx.x & 31;
    const int part = threadIdx.x >> 5;       // 0..7, each owns 96 c's
    const int col  = blockIdx.x * 64 + lane; // and col+32
    const int code = g_codes[b];

    const float* wp = W + (size_t)code * 16 * 768;
    const float* f0 = F + (size_t)b * 768 * 1024 + col;
    const float* f1 = f0 + 32;

    float acc0[16], acc1[16];
    #pragma unroll
    for (int q = 0; q < 16; ++q) { acc0[q] = 0.0f; acc1[q] = 0.0f; }

    const int c0 = part * 96;
    for (int it = 0; it < 12; ++it) {
        const int c = c0 + it * 8;
        float fv0[8], fv1[8];
        #pragma unroll
        for (int u = 0; u < 8; ++u) {
            fv0[u] = __ldg(&f0[(size_t)(c + u) * 1024]);
            fv1[u] = __ldg(&f1[(size_t)(c + u) * 1024]);
        }
        #pragma unroll
        for (int q = 0; q < 16; ++q) {
            const float4 w0 = *(const float4*)&wp[q * 768 + c];
            const float4 w1 = *(const float4*)&wp[q * 768 + c + 4];
            acc0[q] += w0.x * fv0[0] + w0.y * fv0[1] + w0.z * fv0[2] + w0.w * fv0[3];
            acc0[q] += w1.x * fv0[4] + w1.y * fv0[5] + w1.z * fv0[6] + w1.w * fv0[7];
            acc1[q] += w0.x * fv1[0] + w0.y * fv1[1] + w0.z * fv1[2] + w0.w * fv1[3];
            acc1[q] += w1.x * fv1[4] + w1.y * fv1[5] + w1.z * fv1[6] + w1.w * fv1[7];
        }
    }

    #pragma unroll
    for (int q = 0; q < 16; ++q) {
        red[part][q][lane]      = acc0[q];
        red[part][q][lane + 32] = acc1[q];
    }
    __syncthreads();

    if (part == 0) {
        float lsum = 0.0f;
        #pragma unroll
        for (int half = 0; half < 2; ++half) {
            const int cc = col + half * 32;
            float* op = out + (size_t)b * 16 * 1024 + cc;
            const float* qp = Q + (size_t)b * 16 * 1024 + cc;
            #pragma unroll
            for (int q = 0; q < 16; ++q) {
                const int li = lane + half * 32;
                float s = red[0][q][li] + red[1][q][li]
                        + red[2][q][li] + red[3][q][li]
                        + red[4][q][li] + red[5][q][li]
                        + red[6][q][li] + red[7][q][li];
                op[(size_t)q * 1024] = s;
                float d = s - qp[(size_t)q * 1024];
                lsum += d * d;
            }
        }
        #pragma unroll
        for (int off = 16; off > 0; off >>= 1)
            lsum += __shfl_xor_sync(0xffffffffu, lsum, off);
        if (lane == 0)
            g_loss_part[b * 16 + blockIdx.x] = lsum;
    }
}

__global__ void loss_final(float* __restrict__ out)
{
    __shared__ float s[512];
    const int t = threadIdx.x;
    s[t] = g_loss_part[t];
    __syncthreads();
    for (int o = 256; o > 0; o >>= 1) {
        if (t < o) s[t] += s[t + o];
        __syncthreads();
    }
    if (t == 0) out[524320] = s[0] / 524288.0f;
}

extern "C" void kernel_launch(void* const* d_in, const int* in_sizes, int n_in,
                              void* d_out, int out_size)
{
    const float* F = (const float*)d_in[0];
    const float* Q = (const float*)d_in[1];
    const float* W = (const float*)d_in[2];
    float* out = (float*)d_out;

    cudaFuncSetAttribute(dist_gemm_mma,
                         cudaFuncAttributeMaxDynamicSharedMemorySize, DSMEM);

    conv_kernel<<<CONV_F_BLOCKS + CONV_W_BLOCKS, 256>>>(F, W);
    dist_gemm_mma<<<dim3(8, 8, 32), 128, DSMEM>>>(Q);
    argmin_kernel<<<1, 1024>>>(out);
    sel_kernel<<<dim3(16, 32), 256>>>(F, Q, W, out);
    loss_final<<<1, 512>>>(out);
}

// round 15
// speedup vs baseline: 1.0414x; 1.0414x over previous
#include <cuda_runtime.h>
#include <cuda_fp16.h>
#include <cstdint>

// features: [32, 768, 32, 32] -> F[b, c, hw], hw = 1024
// query:    [32, 16, 32, 32]  -> Q[b, q, hw]
// W:        [64, 16, 768]     -> A[r, c], r = k*16+q  (1024 x 768)
//
// dist2[b,k] = sum_{q,hw} (A@F_b - Q)^2 ; codes = argmin_k ; sel = recompute.
// GEMM in pure fp16 mma.sync (dist2 err std ~0.14 << argmin gap ~150).
// sel: fp32 FFMA over fp16-rounded F (norm rel err ~3e-4 << 1e-3 gate),
// W exact fp32; commit_loss from sel exactly.

#define FN   (32 * 768 * 1024)
#define WN   (1024 * 768)

__device__ __half g_Fh[FN];
__device__ __half g_Wh[WN];
__device__ float g_dist2_part[32 * 512];   // [b][k(64)][hwtile(8)]
__device__ int   g_codes[32];
__device__ float g_loss_part[1024];

// ---------------- PTX helpers ----------------
__device__ __forceinline__ uint32_t smem_u32(const void* p) {
    uint32_t a;
    asm("{ .reg .u64 t; cvta.to.shared.u64 t, %1; cvt.u32.u64 %0, t; }" : "=r"(a) : "l"(p));
    return a;
}
__device__ __forceinline__ void cp16(uint32_t dst, const void* src) {
    asm volatile("cp.async.cg.shared.global [%0], [%1], 16;" :: "r"(dst), "l"(src));
}
#define CP_COMMIT() asm volatile("cp.async.commit_group;" ::: "memory")
#define CP_WAIT(n)  asm volatile("cp.async.wait_group %0;" :: "n"(n) : "memory")

__device__ __forceinline__ void ldsm_x4(uint32_t addr, uint32_t* r) {
    asm volatile("ldmatrix.sync.aligned.m8n8.x4.shared.b16 {%0,%1,%2,%3}, [%4];"
                 : "=r"(r[0]), "=r"(r[1]), "=r"(r[2]), "=r"(r[3]) : "r"(addr));
}
__device__ __forceinline__ void ldsm_x4_t(uint32_t addr, uint32_t* r) {
    asm volatile("ldmatrix.sync.aligned.m8n8.x4.trans.shared.b16 {%0,%1,%2,%3}, [%4];"
                 : "=r"(r[0]), "=r"(r[1]), "=r"(r[2]), "=r"(r[3]) : "r"(addr));
}
__device__ __forceinline__ void mma_f16(float* c, const uint32_t* a, const uint32_t* b) {
    asm volatile(
        "mma.sync.aligned.m16n8k16.row.col.f32.f16.f16.f32 "
        "{%0,%1,%2,%3},{%4,%5,%6,%7},{%8,%9},{%0,%1,%2,%3};"
        : "+f"(c[0]), "+f"(c[1]), "+f"(c[2]), "+f"(c[3])
        : "r"(a[0]), "r"(a[1]), "r"(a[2]), "r"(a[3]), "r"(b[0]), "r"(b[1]));
}

// ---------------- fp32 -> fp16 pre-conversion (F and W in one launch) ----------------
#define CONV_F_BLOCKS 2048
#define CONV_W_BLOCKS 192
__global__ void conv_kernel(const float* __restrict__ F, const float* __restrict__ W) {
    if (blockIdx.x < CONV_F_BLOCKS) {
        const float4* src = (const float4*)F;
        __half2* h2 = reinterpret_cast<__half2*>(g_Fh);
        const int n4 = FN / 4;
        for (int i = blockIdx.x * blockDim.x + threadIdx.x; i < n4;
             i += CONV_F_BLOCKS * blockDim.x) {
            float4 v = src[i];
            h2[i * 2 + 0] = __floats2half2_rn(v.x, v.y);
            h2[i * 2 + 1] = __floats2half2_rn(v.z, v.w);
        }
    } else {
        const float4* src = (const float4*)W;
        __half2* h2 = reinterpret_cast<__half2*>(g_Wh);
        const int n4 = WN / 4;
        for (int i = (blockIdx.x - CONV_F_BLOCKS) * blockDim.x + threadIdx.x; i < n4;
             i += CONV_W_BLOCKS * blockDim.x) {
            float4 v = src[i];
            h2[i * 2 + 0] = __floats2half2_rn(v.x, v.y);
            h2[i * 2 + 1] = __floats2half2_rn(v.z, v.w);
        }
    }
}

// ---------------- dist GEMM: fp16 mma.sync (R8 structure, proven) ----------------
#define ST_B    10240
#define STAGE   18944
#define NSTAGE  5
#define DSMEM   (NSTAGE * STAGE + 64)

__device__ __forceinline__ void load_stage(
    int t, int kb, uint32_t sbase, int rowBase, int colBase, size_t Foff)
{
    #pragma unroll
    for (int it = 0; it < 4; ++it) {
        int o = it * 128 + t;
        int row = o >> 2, seg = o & 3;
        const __half* s = g_Wh + (size_t)(rowBase + row) * 768 + kb + seg * 8;
        cp16(sbase + row * 80 + seg * 16, s);
    }
    #pragma unroll
    for (int it = 0; it < 4; ++it) {
        int o = it * 128 + t;
        int row = o >> 4, seg = o & 15;
        const __half* s = g_Fh + Foff + (size_t)(kb + row) * 1024 + colBase + seg * 8;
        cp16(sbase + ST_B + row * 272 + seg * 16, s);
    }
}

__global__ __launch_bounds__(128, 2)
void dist_gemm_mma(const float* __restrict__ Q)
{
    extern __shared__ char smem[];
    const uint32_t sb = smem_u32(smem);
    float* sred = (float*)(smem + NSTAGE * STAGE);   // [8 k][2 colgrp]

    const int t    = threadIdx.x;
    const int wid  = t >> 5;
    const int lane = t & 31;
    const int wr   = wid & 1;
    const int wc   = wid >> 1;
    const int b       = blockIdx.z;
    const int rowBase = blockIdx.y * 128;
    const int colBase = blockIdx.x * 128;
    const size_t Foff = (size_t)b * 768 * 1024;

    uint32_t a_addr[4];
    #pragma unroll
    for (int rt = 0; rt < 4; ++rt) {
        int row = wr * 64 + rt * 16 + (lane & 15);
        a_addr[rt] = sb + row * 80 + ((lane >> 4) * 16);
    }
    uint32_t b_addr[4];
    #pragma unroll
    for (int p = 0; p < 4; ++p) {
        int n = wc * 64 + p * 16 + (lane >> 4) * 8;
        b_addr[p] = sb + ST_B + (lane & 15) * 272 + n * 2;
    }

    float acc[4][8][4];
    #pragma unroll
    for (int i = 0; i < 4; ++i)
        #pragma unroll
        for (int j = 0; j < 8; ++j)
            #pragma unroll
            for (int v = 0; v < 4; ++v) acc[i][j][v] = 0.0f;

    load_stage(t, 0, sb, rowBase, colBase, Foff);
    CP_COMMIT();
    load_stage(t, 32, sb + STAGE, rowBase, colBase, Foff);
    CP_COMMIT();
    load_stage(t, 64, sb + 2 * STAGE, rowBase, colBase, Foff);
    CP_COMMIT();

    for (int kt = 0; kt < 24; ++kt) {
        if (kt + 3 < 24)
            load_stage(t, (kt + 3) * 32, sb + ((kt + 3) % NSTAGE) * STAGE,
                       rowBase, colBase, Foff);
        CP_COMMIT();
        CP_WAIT(3);           // this warp's chunk-kt copies resident
        __syncthreads();      // -> ALL warps' chunk-kt copies visible

        const uint32_t soff = (kt % NSTAGE) * STAGE;
        #pragma unroll
        for (int ks = 0; ks < 2; ++ks) {
            uint32_t ah[4][4], bh[16];
            const uint32_t aoff = soff + ks * 32;
            const uint32_t boff = soff + ks * (16 * 272);
            #pragma unroll
            for (int rt = 0; rt < 4; ++rt)
                ldsm_x4(a_addr[rt] + aoff, ah[rt]);
            #pragma unroll
            for (int p = 0; p < 4; ++p)
                ldsm_x4_t(b_addr[p] + boff, &bh[p * 4]);
            #pragma unroll
            for (int rt = 0; rt < 4; ++rt)
                #pragma unroll
                for (int nt = 0; nt < 8; ++nt)
                    mma_f16(acc[rt][nt], ah[rt], &bh[nt * 2]);
        }
    }

    // ---- epilogue: (C - Q)^2, deterministic reduction per k-group ----
    const int qr0 = lane >> 2;
    const int cb  = colBase + wc * 64;
    float2 qa[8], qb[8];
    #pragma unroll
    for (int nt = 0; nt < 8; ++nt) {
        const float* q0 = Q + (size_t)b * 16384 + (size_t)qr0 * 1024 + cb + nt * 8 + (lane & 3) * 2;
        qa[nt] = *(const float2*)q0;
        qb[nt] = *(const float2*)(q0 + 8 * 1024);
    }
    __syncthreads();
    #pragma unroll
    for (int rt = 0; rt < 4; ++rt) {
        float rs = 0.0f;
        #pragma unroll
        for (int nt = 0; nt < 8; ++nt) {
            float d0 = acc[rt][nt][0] - qa[nt].x;
            float d1 = acc[rt][nt][1] - qa[nt].y;
            float d2 = acc[rt][nt][2] - qb[nt].x;
            float d3 = acc[rt][nt][3] - qb[nt].y;
            rs += d0 * d0 + d1 * d1 + d2 * d2 + d3 * d3;
        }
        #pragma unroll
        for (int off = 16; off > 0; off >>= 1)
            rs += __shfl_xor_sync(0xffffffffu, rs, off);
        if (lane == 0) sred[(wr * 4 + rt) * 2 + wc] = rs;
    }
    __syncthreads();
    if (t < 8) {
        float s = sred[t * 2 + 0] + sred[t * 2 + 1];
        const int k = blockIdx.y * 8 + t;
        g_dist2_part[b * 512 + k * 8 + blockIdx.x] = s;
    }
}

// ---------------- argmin: 1 block, warp-per-batch ----------------
__global__ __launch_bounds__(1024)
void argmin_kernel(float* __restrict__ out)
{
    const int b    = threadIdx.x >> 5;
    const int lane = threadIdx.x & 31;

    float v[2];
    #pragma unroll
    for (int j = 0; j < 2; ++j) {
        const int k = lane * 2 + j;
        const float4* p = (const float4*)(g_dist2_part + b * 512 + k * 8);
        float4 x = p[0], y = p[1];
        v[j] = (x.x + x.y) + (x.z + x.w) + (y.x + y.y) + (y.z + y.w);
    }
    float best = v[0] < v[1] ? v[0] : v[1];
    int   bi   = v[0] < v[1] ? lane * 2 : lane * 2 + 1;
    #pragma unroll
    for (int off = 16; off > 0; off >>= 1) {
        float ov = __shfl_xor_sync(0xffffffffu, best, off);
        int   oi = __shfl_xor_sync(0xffffffffu, bi,   off);
        if (ov < best || (ov == best && oi < bi)) { best = ov; bi = oi; }
    }
    if (lane == 0) {
        g_codes[b] = bi;
        out[524288 + b] = (float)bi;
    }
}

// ---------------- sel recompute + loss partials ----------------
// R13 structure (proven best: 256 thr, 8 c-partitions, 16-deep F batches),
// but F read from the fp16 copy g_Fh: half the DRAM bytes, same MLP.
// W stays exact fp32 (warp-uniform L1-resident __ldg).
__global__ __launch_bounds__(256, 4)
void sel_kernel(const float* __restrict__ Q,
                const float* __restrict__ W,
                float* __restrict__ out)
{
    __shared__ float red[8][16][32];   // 16 KB
    const int b    = blockIdx.y;
    const int lane = threadIdx.x & 31;
    const int part = threadIdx.x >> 5;       // 0..7, each owns 96 c's
    const int col  = blockIdx.x * 32 + lane;
    const int code = g_codes[b];

    const float*  wp = W + (size_t)code * 16 * 768;
    const __half* f  = g_Fh + (size_t)b * 768 * 1024 + col;

    float acc[16];
    #pragma unroll
    for (int q = 0; q < 16; ++q) acc[q] = 0.0f;

    const int c0 = part * 96;
    for (int it = 0; it < 6; ++it) {
        const int c = c0 + it * 16;
        __half hv[16];
        #pragma unroll
        for (int u = 0; u < 16; ++u)
            hv[u] = __ldg(&f[(size_t)(c + u) * 1024]);
        float fv[16];
        #pragma unroll
        for (int u = 0; u < 16; ++u)
            fv[u] = __half2float(hv[u]);
        #pragma unroll
        for (int q = 0; q < 16; ++q) {
            const float4 w0 = *(const float4*)&wp[q * 768 + c];
            const float4 w1 = *(const float4*)&wp[q * 768 + c + 4];
            const float4 w2 = *(const float4*)&wp[q * 768 + c + 8];
            const float4 w3 = *(const float4*)&wp[q * 768 + c + 12];
            acc[q] += w0.x * fv[0]  + w0.y * fv[1]  + w0.z * fv[2]  + w0.w * fv[3];
            acc[q] += w1.x * fv[4]  + w1.y * fv[5]  + w1.z * fv[6]  + w1.w * fv[7];
            acc[q] += w2.x * fv[8]  + w2.y * fv[9]  + w2.z * fv[10] + w2.w * fv[11];
            acc[q] += w3.x * fv[12] + w3.y * fv[13] + w3.z * fv[14] + w3.w * fv[15];
        }
    }

    #pragma unroll
    for (int q = 0; q < 16; ++q) red[part][q][lane] = acc[q];
    __syncthreads();

    if (part == 0) {
        float* op = out + (size_t)b * 16 * 1024 + col;
        const float* qp = Q + (size_t)b * 16 * 1024 + col;
        float lsum = 0.0f;
        #pragma unroll
        for (int q = 0; q < 16; ++q) {
            float s = red[0][q][lane] + red[1][q][lane]
                    + red[2][q][lane] + red[3][q][lane]
                    + red[4][q][lane] + red[5][q][lane]
                    + red[6][q][lane] + red[7][q][lane];
            op[(size_t)q * 1024] = s;
            float d = s - qp[(size_t)q * 1024];
            lsum += d * d;
        }
        #pragma unroll
        for (int off = 16; off > 0; off >>= 1)
            lsum += __shfl_xor_sync(0xffffffffu, lsum, off);
        if (lane == 0)
            g_loss_part[b * 32 + blockIdx.x] = lsum;
    }
}

__global__ void loss_final(float* __restrict__ out)
{
    __shared__ float s[1024];
    const int t = threadIdx.x;
    s[t] = g_loss_part[t];
    __syncthreads();
    for (int o = 512; o > 0; o >>= 1) {
        if (t < o) s[t] += s[t + o];
        __syncthreads();
    }
    if (t == 0) out[524320] = s[0] / 524288.0f;
}

extern "C" void kernel_launch(void* const* d_in, const int* in_sizes, int n_in,
                              void* d_out, int out_size)
{
    const float* F = (const float*)d_in[0];
    const float* Q = (const float*)d_in[1];
    const float* W = (const float*)d_in[2];
    float* out = (float*)d_out;

    cudaFuncSetAttribute(dist_gemm_mma,
                         cudaFuncAttributeMaxDynamicSharedMemorySize, DSMEM);

    conv_kernel<<<CONV_F_BLOCKS + CONV_W_BLOCKS, 256>>>(F, W);
    dist_gemm_mma<<<dim3(8, 8, 32), 128, DSMEM>>>(Q);
    argmin_kernel<<<1, 1024>>>(out);
    sel_kernel<<<dim3(32, 32), 256>>>(Q, W, out);
    loss_final<<<1, 1024>>>(out);
}

// round 16
// speedup vs baseline: 1.1931x; 1.1457x over previous
#include <cuda_runtime.h>
#include <cuda_fp16.h>
#include <cstdint>

// features: [32, 768, 32, 32] -> F[b, c, hw], hw = 1024
// query:    [32, 16, 32, 32]  -> Q[b, q, hw]
// W:        [64, 16, 768]     -> A[r, c], r = k*16+q  (1024 x 768)
//
// dist2[b,k] = sum_{q,hw} (A@F_b - Q)^2 ; codes = argmin_k.
// The dist GEMM stores its full product C[b][r][hw] as fp16; sel is then a
// 16-row gather of C (no recompute). Output rel err ~4.5e-4 (mma fp32-accum
// error + fp16 storage), comfortably under the 1e-3 gate.

#define FN   (32 * 768 * 1024)
#define WN   (1024 * 768)

__device__ __half g_Fh[FN];
__device__ __half g_Wh[WN];
__device__ __half g_C[32 * 1024 * 1024];   // [b][row(1024)][hw(1024)], 64 MB
__device__ float g_dist2_part[32 * 512];   // [b][k(64)][hwtile(8)]
__device__ int   g_codes[32];
__device__ float g_loss_part[32];

// ---------------- PTX helpers ----------------
__device__ __forceinline__ uint32_t smem_u32(const void* p) {
    uint32_t a;
    asm("{ .reg .u64 t; cvta.to.shared.u64 t, %1; cvt.u32.u64 %0, t; }" : "=r"(a) : "l"(p));
    return a;
}
__device__ __forceinline__ void cp16(uint32_t dst, const void* src) {
    asm volatile("cp.async.cg.shared.global [%0], [%1], 16;" :: "r"(dst), "l"(src));
}
#define CP_COMMIT() asm volatile("cp.async.commit_group;" ::: "memory")
#define CP_WAIT(n)  asm volatile("cp.async.wait_group %0;" :: "n"(n) : "memory")

__device__ __forceinline__ void ldsm_x4(uint32_t addr, uint32_t* r) {
    asm volatile("ldmatrix.sync.aligned.m8n8.x4.shared.b16 {%0,%1,%2,%3}, [%4];"
                 : "=r"(r[0]), "=r"(r[1]), "=r"(r[2]), "=r"(r[3]) : "r"(addr));
}
__device__ __forceinline__ void ldsm_x4_t(uint32_t addr, uint32_t* r) {
    asm volatile("ldmatrix.sync.aligned.m8n8.x4.trans.shared.b16 {%0,%1,%2,%3}, [%4];"
                 : "=r"(r[0]), "=r"(r[1]), "=r"(r[2]), "=r"(r[3]) : "r"(addr));
}
__device__ __forceinline__ void mma_f16(float* c, const uint32_t* a, const uint32_t* b) {
    asm volatile(
        "mma.sync.aligned.m16n8k16.row.col.f32.f16.f16.f32 "
        "{%0,%1,%2,%3},{%4,%5,%6,%7},{%8,%9},{%0,%1,%2,%3};"
        : "+f"(c[0]), "+f"(c[1]), "+f"(c[2]), "+f"(c[3])
        : "r"(a[0]), "r"(a[1]), "r"(a[2]), "r"(a[3]), "r"(b[0]), "r"(b[1]));
}

// ---------------- fp32 -> fp16 pre-conversion (F and W in one launch) ----------------
#define CONV_F_BLOCKS 2048
#define CONV_W_BLOCKS 192
__global__ void conv_kernel(const float* __restrict__ F, const float* __restrict__ W) {
    if (blockIdx.x < CONV_F_BLOCKS) {
        const float4* src = (const float4*)F;
        __half2* h2 = reinterpret_cast<__half2*>(g_Fh);
        const int n4 = FN / 4;
        for (int i = blockIdx.x * blockDim.x + threadIdx.x; i < n4;
             i += CONV_F_BLOCKS * blockDim.x) {
            float4 v = src[i];
            h2[i * 2 + 0] = __floats2half2_rn(v.x, v.y);
            h2[i * 2 + 1] = __floats2half2_rn(v.z, v.w);
        }
    } else {
        const float4* src = (const float4*)W;
        __half2* h2 = reinterpret_cast<__half2*>(g_Wh);
        const int n4 = WN / 4;
        for (int i = (blockIdx.x - CONV_F_BLOCKS) * blockDim.x + threadIdx.x; i < n4;
             i += CONV_W_BLOCKS * blockDim.x) {
            float4 v = src[i];
            h2[i * 2 + 0] = __floats2half2_rn(v.x, v.y);
            h2[i * 2 + 1] = __floats2half2_rn(v.z, v.w);
        }
    }
}

// ---------------- dist GEMM: fp16 mma.sync (R8 mainloop, proven) ----------------
#define ST_B    10240
#define STAGE   18944
#define NSTAGE  5
#define DSMEM   (NSTAGE * STAGE + 64)

__device__ __forceinline__ void load_stage(
    int t, int kb, uint32_t sbase, int rowBase, int colBase, size_t Foff)
{
    #pragma unroll
    for (int it = 0; it < 4; ++it) {
        int o = it * 128 + t;
        int row = o >> 2, seg = o & 3;
        const __half* s = g_Wh + (size_t)(rowBase + row) * 768 + kb + seg * 8;
        cp16(sbase + row * 80 + seg * 16, s);
    }
    #pragma unroll
    for (int it = 0; it < 4; ++it) {
        int o = it * 128 + t;
        int row = o >> 4, seg = o & 15;
        const __half* s = g_Fh + Foff + (size_t)(kb + row) * 1024 + colBase + seg * 8;
        cp16(sbase + ST_B + row * 272 + seg * 16, s);
    }
}

__global__ __launch_bounds__(128, 2)
void dist_gemm_mma(const float* __restrict__ Q)
{
    extern __shared__ char smem[];
    const uint32_t sb = smem_u32(smem);
    float* sred = (float*)(smem + NSTAGE * STAGE);   // [8 k][2 colgrp]

    const int t    = threadIdx.x;
    const int wid  = t >> 5;
    const int lane = t & 31;
    const int wr   = wid & 1;
    const int wc   = wid >> 1;
    const int b       = blockIdx.z;
    const int rowBase = blockIdx.y * 128;
    const int colBase = blockIdx.x * 128;
    const size_t Foff = (size_t)b * 768 * 1024;

    uint32_t a_addr[4];
    #pragma unroll
    for (int rt = 0; rt < 4; ++rt) {
        int row = wr * 64 + rt * 16 + (lane & 15);
        a_addr[rt] = sb + row * 80 + ((lane >> 4) * 16);
    }
    uint32_t b_addr[4];
    #pragma unroll
    for (int p = 0; p < 4; ++p) {
        int n = wc * 64 + p * 16 + (lane >> 4) * 8;
        b_addr[p] = sb + ST_B + (lane & 15) * 272 + n * 2;
    }

    float acc[4][8][4];
    #pragma unroll
    for (int i = 0; i < 4; ++i)
        #pragma unroll
        for (int j = 0; j < 8; ++j)
            #pragma unroll
            for (int v = 0; v < 4; ++v) acc[i][j][v] = 0.0f;

    load_stage(t, 0, sb, rowBase, colBase, Foff);
    CP_COMMIT();
    load_stage(t, 32, sb + STAGE, rowBase, colBase, Foff);
    CP_COMMIT();
    load_stage(t, 64, sb + 2 * STAGE, rowBase, colBase, Foff);
    CP_COMMIT();

    for (int kt = 0; kt < 24; ++kt) {
        if (kt + 3 < 24)
            load_stage(t, (kt + 3) * 32, sb + ((kt + 3) % NSTAGE) * STAGE,
                       rowBase, colBase, Foff);
        CP_COMMIT();
        CP_WAIT(3);           // this warp's chunk-kt copies resident
        __syncthreads();      // -> ALL warps' chunk-kt copies visible

        const uint32_t soff = (kt % NSTAGE) * STAGE;
        #pragma unroll
        for (int ks = 0; ks < 2; ++ks) {
            uint32_t ah[4][4], bh[16];
            const uint32_t aoff = soff + ks * 32;
            const uint32_t boff = soff + ks * (16 * 272);
            #pragma unroll
            for (int rt = 0; rt < 4; ++rt)
                ldsm_x4(a_addr[rt] + aoff, ah[rt]);
            #pragma unroll
            for (int p = 0; p < 4; ++p)
                ldsm_x4_t(b_addr[p] + boff, &bh[p * 4]);
            #pragma unroll
            for (int rt = 0; rt < 4; ++rt)
                #pragma unroll
                for (int nt = 0; nt < 8; ++nt)
                    mma_f16(acc[rt][nt], ah[rt], &bh[nt * 2]);
        }
    }

    // ---- epilogue: store C as fp16 + (C - Q)^2 reduction per k-group ----
    const int qr0 = lane >> 2;
    const int cb  = colBase + wc * 64;
    float2 qa[8], qb[8];
    #pragma unroll
    for (int nt = 0; nt < 8; ++nt) {
        const float* q0 = Q + (size_t)b * 16384 + (size_t)qr0 * 1024 + cb + nt * 8 + (lane & 3) * 2;
        qa[nt] = *(const float2*)q0;
        qb[nt] = *(const float2*)(q0 + 8 * 1024);
    }
    // C store: row0 = rowBase + wr*64 + rt*16 + (lane>>2), row1 = row0 + 8,
    // col = cb + nt*8 + (lane&3)*2  (half2 per pair)
    {
        const size_t cbase = ((size_t)b << 20);
        #pragma unroll
        for (int rt = 0; rt < 4; ++rt) {
            const int row0 = rowBase + wr * 64 + rt * 16 + (lane >> 2);
            __half* p0 = g_C + cbase + (size_t)row0 * 1024 + cb + (lane & 3) * 2;
            __half* p1 = p0 + 8 * 1024;
            #pragma unroll
            for (int nt = 0; nt < 8; ++nt) {
                *(__half2*)(p0 + nt * 8) = __floats2half2_rn(acc[rt][nt][0], acc[rt][nt][1]);
                *(__half2*)(p1 + nt * 8) = __floats2half2_rn(acc[rt][nt][2], acc[rt][nt][3]);
            }
        }
    }
    __syncthreads();
    #pragma unroll
    for (int rt = 0; rt < 4; ++rt) {
        float rs = 0.0f;
        #pragma unroll
        for (int nt = 0; nt < 8; ++nt) {
            float d0 = acc[rt][nt][0] - qa[nt].x;
            float d1 = acc[rt][nt][1] - qa[nt].y;
            float d2 = acc[rt][nt][2] - qb[nt].x;
            float d3 = acc[rt][nt][3] - qb[nt].y;
            rs += d0 * d0 + d1 * d1 + d2 * d2 + d3 * d3;
        }
        #pragma unroll
        for (int off = 16; off > 0; off >>= 1)
            rs += __shfl_xor_sync(0xffffffffu, rs, off);
        if (lane == 0) sred[(wr * 4 + rt) * 2 + wc] = rs;
    }
    __syncthreads();
    if (t < 8) {
        float s = sred[t * 2 + 0] + sred[t * 2 + 1];
        const int k = blockIdx.y * 8 + t;
        g_dist2_part[b * 512 + k * 8 + blockIdx.x] = s;
    }
}

// ---------------- argmin: 1 block, warp-per-batch ----------------
__global__ __launch_bounds__(1024)
void argmin_kernel(float* __restrict__ out)
{
    const int b    = threadIdx.x >> 5;
    const int lane = threadIdx.x & 31;

    float v[2];
    #pragma unroll
    for (int j = 0; j < 2; ++j) {
        const int k = lane * 2 + j;
        const float4* p = (const float4*)(g_dist2_part + b * 512 + k * 8);
        float4 x = p[0], y = p[1];
        v[j] = (x.x + x.y) + (x.z + x.w) + (y.x + y.y) + (y.z + y.w);
    }
    float best = v[0] < v[1] ? v[0] : v[1];
    int   bi   = v[0] < v[1] ? lane * 2 : lane * 2 + 1;
    #pragma unroll
    for (int off = 16; off > 0; off >>= 1) {
        float ov = __shfl_xor_sync(0xffffffffu, best, off);
        int   oi = __shfl_xor_sync(0xffffffffu, bi,   off);
        if (ov < best || (ov == best && oi < bi)) { best = ov; bi = oi; }
    }
    if (lane == 0) {
        g_codes[b] = bi;
        out[524288 + b] = (float)bi;
    }
}

// ---------------- gather: sel = C rows of the winning code + loss ----------------
// 32 blocks (one per batch), 256 threads. Copies C[b][code*16..+16][:] (fp16)
// to out (fp32) and accumulates commit_loss partials.
__global__ __launch_bounds__(256)
void gather_kernel(const float* __restrict__ Q, float* __restrict__ out)
{
    __shared__ float sl[256];
    const int b = blockIdx.x;
    const int code = g_codes[b];
    const __half2* src = (const __half2*)(g_C + ((size_t)b << 20) + (size_t)code * 16 * 1024);
    float* dst = out + (size_t)b * 16384;
    const float* qp = Q + (size_t)b * 16384;

    float lsum = 0.0f;
    // 16384 halves = 8192 half2; 4 half2 per thread-iter (8 floats)
    for (int i = threadIdx.x; i < 2048; i += 256) {
        const int e = i * 4;
        __half2 h0 = src[e + 0], h1 = src[e + 1], h2 = src[e + 2], h3 = src[e + 3];
        float2 v0 = __half22float2(h0), v1 = __half22float2(h1);
        float2 v2 = __half22float2(h2), v3 = __half22float2(h3);
        float4 o0 = make_float4(v0.x, v0.y, v1.x, v1.y);
        float4 o1 = make_float4(v2.x, v2.y, v3.x, v3.y);
        *(float4*)(dst + e * 2)     = o0;
        *(float4*)(dst + e * 2 + 4) = o1;
        const float4 q0 = *(const float4*)(qp + e * 2);
        const float4 q1 = *(const float4*)(qp + e * 2 + 4);
        float d;
        d = o0.x - q0.x; lsum += d * d;
        d = o0.y - q0.y; lsum += d * d;
        d = o0.z - q0.z; lsum += d * d;
        d = o0.w - q0.w; lsum += d * d;
        d = o1.x - q1.x; lsum += d * d;
        d = o1.y - q1.y; lsum += d * d;
        d = o1.z - q1.z; lsum += d * d;
        d = o1.w - q1.w; lsum += d * d;
    }
    sl[threadIdx.x] = lsum;
    __syncthreads();
    for (int o = 128; o > 0; o >>= 1) {
        if (threadIdx.x < o) sl[threadIdx.x] += sl[threadIdx.x + o];
        __syncthreads();
    }
    if (threadIdx.x == 0) g_loss_part[b] = sl[0];
}

__global__ void loss_final(float* __restrict__ out)
{
    __shared__ float s[32];
    s[threadIdx.x] = g_loss_part[threadIdx.x];
    __syncthreads();
    if (threadIdx.x == 0) {
        float t = 0.0f;
        #pragma unroll
        for (int i = 0; i < 32; ++i) t += s[i];
        out[524320] = t / 524288.0f;
    }
}

extern "C" void kernel_launch(void* const* d_in, const int* in_sizes, int n_in,
                              void* d_out, int out_size)
{
    const float* F = (const float*)d_in[0];
    const float* Q = (const float*)d_in[1];
    const float* W = (const float*)d_in[2];
    float* out = (float*)d_out;

    cudaFuncSetAttribute(dist_gemm_mma,
                         cudaFuncAttributeMaxDynamicSharedMemorySize, DSMEM);

    conv_kernel<<<CONV_F_BLOCKS + CONV_W_BLOCKS, 256>>>(F, W);
    dist_gemm_mma<<<dim3(8, 8, 32), 128, DSMEM>>>(Q);
    argmin_kernel<<<1, 1024>>>(out);
    gather_kernel<<<32, 256>>>(Q, out);
    loss_final<<<1, 32>>>(out);
}

// round 17
// speedup vs baseline: 1.2496x; 1.0474x over previous
#include <cuda_runtime.h>
#include <cuda_fp16.h>
#include <cstdint>

// features: [32, 768, 32, 32] -> F[b, c, hw], hw = 1024
// query:    [32, 16, 32, 32]  -> Q[b, q, hw]
// W:        [64, 16, 768]     -> A[r, c], r = k*16+q  (1024 x 768)
//
// dist2[b,k] = sum_{q,hw} (A@F_b - Q)^2 ; codes = argmin_k.
// The dist GEMM stores its full product C[b][r][hw] as fp16 (streaming);
// sel is a 16-row gather of C. Output rel err ~4e-4 < 1e-3 gate.

#define FN   (32 * 768 * 1024)
#define WN   (1024 * 768)

__device__ __half g_Fh[FN];
__device__ __half g_Wh[WN];
__device__ __half g_C[32 * 1024 * 1024];   // [b][row(1024)][hw(1024)], 64 MB
__device__ float g_dist2_part[32 * 512];   // [b][k(64)][hwtile(8)]
__device__ float g_loss_part[256];

// ---------------- PTX helpers ----------------
__device__ __forceinline__ uint32_t smem_u32(const void* p) {
    uint32_t a;
    asm("{ .reg .u64 t; cvta.to.shared.u64 t, %1; cvt.u32.u64 %0, t; }" : "=r"(a) : "l"(p));
    return a;
}
__device__ __forceinline__ void cp16(uint32_t dst, const void* src) {
    asm volatile("cp.async.cg.shared.global [%0], [%1], 16;" :: "r"(dst), "l"(src));
}
#define CP_COMMIT() asm volatile("cp.async.commit_group;" ::: "memory")
#define CP_WAIT(n)  asm volatile("cp.async.wait_group %0;" :: "n"(n) : "memory")

__device__ __forceinline__ void ldsm_x4(uint32_t addr, uint32_t* r) {
    asm volatile("ldmatrix.sync.aligned.m8n8.x4.shared.b16 {%0,%1,%2,%3}, [%4];"
                 : "=r"(r[0]), "=r"(r[1]), "=r"(r[2]), "=r"(r[3]) : "r"(addr));
}
__device__ __forceinline__ void ldsm_x4_t(uint32_t addr, uint32_t* r) {
    asm volatile("ldmatrix.sync.aligned.m8n8.x4.trans.shared.b16 {%0,%1,%2,%3}, [%4];"
                 : "=r"(r[0]), "=r"(r[1]), "=r"(r[2]), "=r"(r[3]) : "r"(addr));
}
__device__ __forceinline__ void mma_f16(float* c, const uint32_t* a, const uint32_t* b) {
    asm volatile(
        "mma.sync.aligned.m16n8k16.row.col.f32.f16.f16.f32 "
        "{%0,%1,%2,%3},{%4,%5,%6,%7},{%8,%9},{%0,%1,%2,%3};"
        : "+f"(c[0]), "+f"(c[1]), "+f"(c[2]), "+f"(c[3])
        : "r"(a[0]), "r"(a[1]), "r"(a[2]), "r"(a[3]), "r"(b[0]), "r"(b[1]));
}
// streaming 4-byte global store (evict-first; C is written once, read ~1.5%)
__device__ __forceinline__ void stg_cs32(void* p, uint32_t v) {
    asm volatile("st.global.cs.u32 [%0], %1;" :: "l"(p), "r"(v) : "memory");
}
__device__ __forceinline__ uint32_t h2bits(__half2 h) {
    return *reinterpret_cast<uint32_t*>(&h);
}

// ---------------- fp32 -> fp16 pre-conversion (F and W in one launch) ----------------
#define CONV_F_BLOCKS 2048
#define CONV_W_BLOCKS 192
__global__ void conv_kernel(const float* __restrict__ F, const float* __restrict__ W) {
    if (blockIdx.x < CONV_F_BLOCKS) {
        const float4* src = (const float4*)F;
        __half2* h2 = reinterpret_cast<__half2*>(g_Fh);
        const int n4 = FN / 4;
        for (int i = blockIdx.x * blockDim.x + threadIdx.x; i < n4;
             i += CONV_F_BLOCKS * blockDim.x) {
            float4 v = src[i];
            h2[i * 2 + 0] = __floats2half2_rn(v.x, v.y);
            h2[i * 2 + 1] = __floats2half2_rn(v.z, v.w);
        }
    } else {
        const float4* src = (const float4*)W;
        __half2* h2 = reinterpret_cast<__half2*>(g_Wh);
        const int n4 = WN / 4;
        for (int i = (blockIdx.x - CONV_F_BLOCKS) * blockDim.x + threadIdx.x; i < n4;
             i += CONV_W_BLOCKS * blockDim.x) {
            float4 v = src[i];
            h2[i * 2 + 0] = __floats2half2_rn(v.x, v.y);
            h2[i * 2 + 1] = __floats2half2_rn(v.z, v.w);
        }
    }
}

// ---------------- dist GEMM: fp16 mma.sync (R8 mainloop, proven) ----------------
#define ST_B    10240
#define STAGE   18944
#define NSTAGE  5
#define DSMEM   (NSTAGE * STAGE + 64)

__device__ __forceinline__ void load_stage(
    int t, int kb, uint32_t sbase, int rowBase, int colBase, size_t Foff)
{
    #pragma unroll
    for (int it = 0; it < 4; ++it) {
        int o = it * 128 + t;
        int row = o >> 2, seg = o & 3;
        const __half* s = g_Wh + (size_t)(rowBase + row) * 768 + kb + seg * 8;
        cp16(sbase + row * 80 + seg * 16, s);
    }
    #pragma unroll
    for (int it = 0; it < 4; ++it) {
        int o = it * 128 + t;
        int row = o >> 4, seg = o & 15;
        const __half* s = g_Fh + Foff + (size_t)(kb + row) * 1024 + colBase + seg * 8;
        cp16(sbase + ST_B + row * 272 + seg * 16, s);
    }
}

__global__ __launch_bounds__(128, 2)
void dist_gemm_mma(const float* __restrict__ Q)
{
    extern __shared__ char smem[];
    const uint32_t sb = smem_u32(smem);
    float* sred = (float*)(smem + NSTAGE * STAGE);   // [8 k][2 colgrp]

    const int t    = threadIdx.x;
    const int wid  = t >> 5;
    const int lane = t & 31;
    const int wr   = wid & 1;
    const int wc   = wid >> 1;
    const int b       = blockIdx.z;
    const int rowBase = blockIdx.y * 128;
    const int colBase = blockIdx.x * 128;
    const size_t Foff = (size_t)b * 768 * 1024;

    uint32_t a_addr[4];
    #pragma unroll
    for (int rt = 0; rt < 4; ++rt) {
        int row = wr * 64 + rt * 16 + (lane & 15);
        a_addr[rt] = sb + row * 80 + ((lane >> 4) * 16);
    }
    uint32_t b_addr[4];
    #pragma unroll
    for (int p = 0; p < 4; ++p) {
        int n = wc * 64 + p * 16 + (lane >> 4) * 8;
        b_addr[p] = sb + ST_B + (lane & 15) * 272 + n * 2;
    }

    float acc[4][8][4];
    #pragma unroll
    for (int i = 0; i < 4; ++i)
        #pragma unroll
        for (int j = 0; j < 8; ++j)
            #pragma unroll
            for (int v = 0; v < 4; ++v) acc[i][j][v] = 0.0f;

    load_stage(t, 0, sb, rowBase, colBase, Foff);
    CP_COMMIT();
    load_stage(t, 32, sb + STAGE, rowBase, colBase, Foff);
    CP_COMMIT();
    load_stage(t, 64, sb + 2 * STAGE, rowBase, colBase, Foff);
    CP_COMMIT();

    for (int kt = 0; kt < 24; ++kt) {
        if (kt + 3 < 24)
            load_stage(t, (kt + 3) * 32, sb + ((kt + 3) % NSTAGE) * STAGE,
                       rowBase, colBase, Foff);
        CP_COMMIT();
        CP_WAIT(3);           // this warp's chunk-kt copies resident
        __syncthreads();      // -> ALL warps' chunk-kt copies visible

        const uint32_t soff = (kt % NSTAGE) * STAGE;
        #pragma unroll
        for (int ks = 0; ks < 2; ++ks) {
            uint32_t ah[4][4], bh[16];
            const uint32_t aoff = soff + ks * 32;
            const uint32_t boff = soff + ks * (16 * 272);
            #pragma unroll
            for (int rt = 0; rt < 4; ++rt)
                ldsm_x4(a_addr[rt] + aoff, ah[rt]);
            #pragma unroll
            for (int p = 0; p < 4; ++p)
                ldsm_x4_t(b_addr[p] + boff, &bh[p * 4]);
            #pragma unroll
            for (int rt = 0; rt < 4; ++rt)
                #pragma unroll
                for (int nt = 0; nt < 8; ++nt)
                    mma_f16(acc[rt][nt], ah[rt], &bh[nt * 2]);
        }
    }

    // ---- epilogue: store C (fp16, streaming) + (C - Q)^2 reduction ----
    const int qr0 = lane >> 2;
    const int cb  = colBase + wc * 64;
    float2 qa[8], qb[8];
    #pragma unroll
    for (int nt = 0; nt < 8; ++nt) {
        const float* q0 = Q + (size_t)b * 16384 + (size_t)qr0 * 1024 + cb + nt * 8 + (lane & 3) * 2;
        qa[nt] = *(const float2*)q0;
        qb[nt] = *(const float2*)(q0 + 8 * 1024);
    }
    {
        const size_t cbase = ((size_t)b << 20);
        #pragma unroll
        for (int rt = 0; rt < 4; ++rt) {
            const int row0 = rowBase + wr * 64 + rt * 16 + (lane >> 2);
            __half* p0 = g_C + cbase + (size_t)row0 * 1024 + cb + (lane & 3) * 2;
            __half* p1 = p0 + 8 * 1024;
            #pragma unroll
            for (int nt = 0; nt < 8; ++nt) {
                stg_cs32(p0 + nt * 8, h2bits(__floats2half2_rn(acc[rt][nt][0], acc[rt][nt][1])));
                stg_cs32(p1 + nt * 8, h2bits(__floats2half2_rn(acc[rt][nt][2], acc[rt][nt][3])));
            }
        }
    }
    __syncthreads();
    #pragma unroll
    for (int rt = 0; rt < 4; ++rt) {
        float rs = 0.0f;
        #pragma unroll
        for (int nt = 0; nt < 8; ++nt) {
            float d0 = acc[rt][nt][0] - qa[nt].x;
            float d1 = acc[rt][nt][1] - qa[nt].y;
            float d2 = acc[rt][nt][2] - qb[nt].x;
            float d3 = acc[rt][nt][3] - qb[nt].y;
            rs += d0 * d0 + d1 * d1 + d2 * d2 + d3 * d3;
        }
        #pragma unroll
        for (int off = 16; off > 0; off >>= 1)
            rs += __shfl_xor_sync(0xffffffffu, rs, off);
        if (lane == 0) sred[(wr * 4 + rt) * 2 + wc] = rs;
    }
    __syncthreads();
    if (t < 8) {
        float s = sred[t * 2 + 0] + sred[t * 2 + 1];
        const int k = blockIdx.y * 8 + t;
        g_dist2_part[b * 512 + k * 8 + blockIdx.x] = s;
    }
}

// ---------------- gather (+per-block argmin): 256 blocks = 32 b x 8 slices --
// Each block recomputes its batch's argmin (deterministic, identical across
// the 8 sibling blocks), then copies 2 of the 16 winning C rows to out and
// accumulates loss partials. Block (b, s) handles rows 2s..2s+1.
__global__ __launch_bounds__(256)
void gather_kernel(const float* __restrict__ Q, float* __restrict__ out)
{
    __shared__ float sv[64];
    __shared__ float sl[256];
    __shared__ int   scode;
    const int b = blockIdx.x >> 3;
    const int s = blockIdx.x & 7;
    const int t = threadIdx.x;

    // ---- argmin over k (threads 0..63 each sum one k's 8 partials) ----
    if (t < 64) {
        const float4* p = (const float4*)(g_dist2_part + b * 512 + t * 8);
        float4 x = p[0], y = p[1];
        sv[t] = (x.x + x.y) + (x.z + x.w) + (y.x + y.y) + (y.z + y.w);
    }
    __syncthreads();
    if (t < 32) {
        float v0 = sv[t], v1 = sv[t + 32];
        float best = v0 < v1 ? v0 : v1;
        int   bi   = v0 < v1 ? t : t + 32;
        #pragma unroll
        for (int off = 16; off > 0; off >>= 1) {
            float ov = __shfl_xor_sync(0xffffffffu, best, off);
            int   oi = __shfl_xor_sync(0xffffffffu, bi,   off);
            if (ov < best || (ov == best && oi < bi)) { best = ov; bi = oi; }
        }
        if (t == 0) {
            scode = bi;
            if (s == 0) out[524288 + b] = (float)bi;
        }
    }
    __syncthreads();
    const int code = scode;

    // ---- gather 2 rows (2048 floats) + loss partials ----
    const size_t roff = (size_t)(code * 16 + s * 2) * 1024;
    const __half2* src = (const __half2*)(g_C + ((size_t)b << 20) + roff);
    float* dst = out + (size_t)b * 16384 + (size_t)s * 2048;
    const float* qp = Q + (size_t)b * 16384 + (size_t)s * 2048;

    float lsum = 0.0f;
    // 2048 floats = 1024 half2; 4 half2 (8 floats) per thread-iter, 256 thr
    {
        const int i = t;
        const int e = i * 4;
        __half2 h0 = src[e + 0], h1 = src[e + 1], h2 = src[e + 2], h3 = src[e + 3];
        float2 v0 = __half22float2(h0), v1 = __half22float2(h1);
        float2 v2 = __half22float2(h2), v3 = __half22float2(h3);
        float4 o0 = make_float4(v0.x, v0.y, v1.x, v1.y);
        float4 o1 = make_float4(v2.x, v2.y, v3.x, v3.y);
        *(float4*)(dst + e * 2)     = o0;
        *(float4*)(dst + e * 2 + 4) = o1;
        const float4 q0 = *(const float4*)(qp + e * 2);
        const float4 q1 = *(const float4*)(qp + e * 2 + 4);
        float d;
        d = o0.x - q0.x; lsum += d * d;
        d = o0.y - q0.y; lsum += d * d;
        d = o0.z - q0.z; lsum += d * d;
        d = o0.w - q0.w; lsum += d * d;
        d = o1.x - q1.x; lsum += d * d;
        d = o1.y - q1.y; lsum += d * d;
        d = o1.z - q1.z; lsum += d * d;
        d = o1.w - q1.w; lsum += d * d;
    }
    sl[t] = lsum;
    __syncthreads();
    for (int o = 128; o > 0; o >>= 1) {
        if (t < o) sl[t] += sl[t + o];
        __syncthreads();
    }
    if (t == 0) g_loss_part[blockIdx.x] = sl[0];
}

__global__ void loss_final(float* __restrict__ out)
{
    __shared__ float s[256];
    const int t = threadIdx.x;
    s[t] = g_loss_part[t];
    __syncthreads();
    for (int o = 128; o > 0; o >>= 1) {
        if (t < o) s[t] += s[t + o];
        __syncthreads();
    }
    if (t == 0) out[524320] = s[0] / 524288.0f;
}

extern "C" void kernel_launch(void* const* d_in, const int* in_sizes, int n_in,
                              void* d_out, int out_size)
{
    const float* F = (const float*)d_in[0];
    const float* Q = (const float*)d_in[1];
    const float* W = (const float*)d_in[2];
    float* out = (float*)d_out;

    cudaFuncSetAttribute(dist_gemm_mma,
                         cudaFuncAttributeMaxDynamicSharedMemorySize, DSMEM);

    conv_kernel<<<CONV_F_BLOCKS + CONV_W_BLOCKS, 256>>>(F, W);
    dist_gemm_mma<<<dim3(8, 8, 32), 128, DSMEM>>>(Q);
    gather_kernel<<<256, 256>>>(Q, out);
    loss_final<<<1, 256>>>(out);
}